// round 11
// baseline (speedup 1.0000x reference)
#include <cuda_runtime.h>

#define PI_F 3.14159265358979323846f
typedef unsigned long long u64;

static __device__ __forceinline__ void cmul(float ar,float ai,float br,float bi,float&cr,float&ci){
  cr = ar*br - ai*bi; ci = ar*bi + ai*br;
}

// ---- f32x2 packed helpers ----
static __device__ __forceinline__ u64 PK2(float lo, float hi){
  u64 r; asm("mov.b64 %0,{%1,%2};":"=l"(r):"f"(lo),"f"(hi)); return r;
}
static __device__ __forceinline__ void UPK(u64 v, float&lo, float&hi){
  asm("mov.b64 {%0,%1},%2;":"=f"(lo),"=f"(hi):"l"(v));
}
static __device__ __forceinline__ u64 SWP(u64 v){
  u64 r; asm("{\n\t.reg .b32 a,b;\n\tmov.b64 {a,b},%1;\n\tmov.b64 %0,{b,a};\n\t}":"=l"(r):"l"(v)); return r;
}
static __device__ __forceinline__ u64 ADDX(u64 a,u64 b){
  u64 r; asm("add.rn.f32x2 %0,%1,%2;":"=l"(r):"l"(a),"l"(b)); return r;
}
static __device__ __forceinline__ u64 MULX(u64 a,u64 b){
  u64 r; asm("mul.rn.f32x2 %0,%1,%2;":"=l"(r):"l"(a),"l"(b)); return r;
}
static __device__ __forceinline__ u64 FMX(u64 a,u64 b,u64 c){
  u64 r; asm("fma.rn.f32x2 %0,%1,%2,%3;":"=l"(r):"l"(a),"l"(b),"l"(c)); return r;
}
static __device__ __forceinline__ float SQRTA(float x){
  float r; asm("sqrt.approx.f32 %0,%1;":"=f"(r):"f"(x)); return r;
}

#define C_NEG1 0xBF800000BF800000ULL  /* (-1,-1) */
#define C_P1M1 0xBF8000003F800000ULL  /* (+1,-1) */
#define C_M1P1 0x3F800000BF800000ULL  /* (-1,+1) */
#define C_CC   0x3F3504F33F3504F3ULL  /* ( C, C) */
#define C_CMC  0xBF3504F33F3504F3ULL  /* ( C,-C) */

// packed DFT-8
static __device__ __forceinline__ void dft8p(u64 x[8]){
  u64 u0=ADDX(x[0],x[4]), u1=FMX(x[4],C_NEG1,x[0]);
  u64 u2=ADDX(x[2],x[6]), u3=FMX(x[6],C_NEG1,x[2]);
  u64 v0=ADDX(x[1],x[5]), v1=FMX(x[5],C_NEG1,x[1]);
  u64 v2=ADDX(x[3],x[7]), v3=FMX(x[7],C_NEG1,x[3]);
  u64 E0=ADDX(u0,u2),     E2=FMX(u2,C_NEG1,u0);
  u64 su3=SWP(u3);
  u64 E1=FMX(su3,C_P1M1,u1), E3=FMX(su3,C_M1P1,u1);
  u64 O0=ADDX(v0,v2),     O2=FMX(v2,C_NEG1,v0);
  u64 sv3=SWP(v3);
  u64 O1=FMX(sv3,C_P1M1,v1), O3=FMX(sv3,C_M1P1,v1);
  u64 t1=FMX(SWP(O1),C_P1M1,O1);
  u64 w1=MULX(t1,C_CC);
  u64 sO2=SWP(O2);
  u64 t3=FMX(O3,C_M1P1,SWP(O3));
  u64 w3=MULX(t3,C_CMC);
  x[0]=ADDX(E0,O0);  x[4]=FMX(O0,C_NEG1,E0);
  x[1]=ADDX(E1,w1);  x[5]=FMX(w1,C_NEG1,E1);
  x[2]=FMX(sO2,C_P1M1,E2); x[6]=FMX(sO2,C_M1P1,E2);
  x[3]=ADDX(E3,w3);  x[7]=FMX(w3,C_NEG1,E3);
}

// swizzled slot for frequency k (conflict-free writes and consecutive-k reads)
static __device__ __forceinline__ int sig_idx(int k){
  return (k & ~7) | ((k + (k>>3)) & 7);
}

// bits j (0..15) with lo <= base1+j <= hi
static __device__ __forceinline__ unsigned wmask(int lo, int hi, int base1){
  int jlo = lo - base1, jhi = hi - base1;
  jlo = max(jlo, 0); jhi = min(jhi, 15);
  if (jhi < jlo) return 0u;
  return (0xFFFFu << jlo) & (0xFFFFu >> (15 - jhi));
}

// order-preserving float<->uint key (no NaNs in data)
static __device__ __forceinline__ unsigned okey(float x){
  unsigned u = __float_as_uint(x);
  return u ^ ((unsigned)(((int)u)>>31) | 0x80000000u);
}
static __device__ __forceinline__ float okey_inv(unsigned k){
  unsigned u = (k & 0x80000000u) ? (k ^ 0x80000000u) : ~k;
  return __uint_as_float(u);
}

__global__ void __launch_bounds__(128, 9)
feat_kernel(const float* __restrict__ x, float* __restrict__ out)
{
  __shared__ __align__(16) float s_sig[2048];
  __shared__ __align__(16) float2 s_d[1088];  // passes 1-2: pad i+(i>>4); final: sigma(k)
  __shared__ float scr[20];
  __shared__ float chunkP[128];
  __shared__ float warptot[4];
  __shared__ float qP[5];
  __shared__ int   iscr[32];   // phase1: [0..19], phase2: [20..31]
  __shared__ int   sh_v1, sh_li, sh_ri;

  const int tid  = threadIdx.x;   // 0..127
  const int lane = tid & 31;
  const int warp = tid >> 5;
  const size_t row = blockIdx.x;
  const float* xp = x + row * 2048;

  // ============ 1024-pt complex FFT of z_n = x[2n] + i x[2n+1], DIF 8,8,8,2 ============
  u64 X[8];
  float mx=-3.0e38f, mn=3.0e38f;
  u64 smv=0ULL, sqv=0ULL;

  // ---- pass 1: coalesced LDG.64; mirror to smem (conflict-free STS.64) ----
  {
    const u64* zin = (const u64*)xp;
    u64* ssg = (u64*)s_sig;
    #pragma unroll
    for (int m=0;m<8;m++){
      u64 z = zin[tid + (m<<7)];
      ssg[tid + (m<<7)] = z;
      float zx,zy; UPK(z,zx,zy);
      mx=fmaxf(mx,fmaxf(zx,zy)); mn=fminf(mn,fminf(zx,zy));
      smv = ADDX(smv, z);
      sqv = FMX(z, z, sqv);
      X[m] = z;
    }
    dft8p(X);
    float sn,cs; __sincosf(-2.f*PI_F*(float)tid*(1.f/1024.f), &sn, &cs);
    const int ob = tid + (tid>>4);
    *(u64*)&s_d[ob] = X[0];
    float wr=cs, wi=sn;
    #pragma unroll
    for (int q=1;q<8;q++){
      float xr,xi; UPK(X[q],xr,xi);
      float rr,ii; cmul(xr,xi,wr,wi,rr,ii);
      s_d[ob + 136*q] = make_float2(rr,ii);
      float nr,ni; cmul(wr,wi,cs,sn,nr,ni); wr=nr; wi=ni;
    }
  }
  __syncthreads();

  // ---- pass 2 ----
  {
    const int sub = tid>>4, tt = tid&15;
    const int ob = 136*sub + tt;
    #pragma unroll
    for (int m=0;m<8;m++) X[m] = *(const u64*)&s_d[ob + 17*m];
    dft8p(X);
    float sn,cs; __sincosf(-2.f*PI_F*(float)tt*(1.f/128.f), &sn, &cs);
    float wr=cs, wi=sn;
    *(u64*)&s_d[ob] = X[0];
    #pragma unroll
    for (int q=1;q<8;q++){
      float xr,xi; UPK(X[q],xr,xi);
      float rr,ii; cmul(xr,xi,wr,wi,rr,ii);
      s_d[ob + 17*q] = make_float2(rr,ii);
      float nr,ni; cmul(wr,wi,cs,sn,nr,ni); wr=nr; wi=ni;
    }
  }
  __syncthreads();

  // ---- pass 3 + radix-2 (shuffle partner tid^16); compile-time W16^q ----
  {
    const int tt  = (tid>>4)&1;
    const int sid = (tid&15) | ((tid>>5)<<4);   // 0..63
    const int ob  = 17*sid + tt;
    #pragma unroll
    for (int m=0;m<8;m++) X[m] = *(const u64*)&s_d[ob + 2*m];
    dft8p(X);
    if (tt){
      const float WR[8] = {1.f,  0.92387953251128675613f,  0.70710678118654752440f,
                            0.38268343236508977173f, 0.f, -0.38268343236508977173f,
                           -0.70710678118654752440f, -0.92387953251128675613f};
      const float WI[8] = {0.f, -0.38268343236508977173f, -0.70710678118654752440f,
                           -0.92387953251128675613f, -1.f, -0.92387953251128675613f,
                           -0.70710678118654752440f, -0.38268343236508977173f};
      #pragma unroll
      for (int q=1;q<8;q++){
        float xr,xi; UPK(X[q],xr,xi);
        X[q] = PK2(xr*WR[q] - xi*WI[q], xr*WI[q] + xi*WR[q]);
      }
    }
    u64 Y[8];
    #pragma unroll
    for (int q=0;q<8;q++){
      u64 other = __shfl_xor_sync(0xffffffffu, X[q], 16);
      Y[q] = tt ? FMX(X[q], C_NEG1, other)   // A - B
                : ADDX(X[q], other);         // A + B
    }
    __syncthreads();   // pass-3 reads done before sigma-layout overwrite
    const int e = sid & 7, f = sid >> 3;
    const int s0 = (e<<3) | ((f+e)&7) | (tt<<9);
    #pragma unroll
    for (int q=0;q<8;q++) *(u64*)&s_d[s0 + (q<<6)] = Y[q];
  }
  __syncthreads();

  // ---- unpack real-FFT magnitudes ----
  float mag = 0.f;
  {
    const float W128r =  0.92387953251128675613f;
    const float W128i = -0.38268343236508977173f;
    int k0 = 1 + tid;
    float wr, wi; __sincosf(-PI_F*(float)k0*(1.f/1024.f), &wi, &wr);
    float lastpair = 0.f;
    #pragma unroll
    for (int c=0;c<4;c++){
      int k  = k0 + (c<<7);
      int k2 = 1024 - k;
      float2 Z1 = s_d[sig_idx(k)];
      float2 Z2 = s_d[sig_idx(k2)];
      float Er = Z1.x + Z2.x;
      float Ei = Z1.y - Z2.y;
      float Or = Z1.y + Z2.y;
      float Oi = Z2.x - Z1.x;
      float Tr = wr*Or - wi*Oi;
      float Ti = wr*Oi + wi*Or;
      float n1 = (Er+Tr)*(Er+Tr) + (Ei+Ti)*(Ei+Ti);
      float n2 = (Er-Tr)*(Er-Tr) + (Ei-Ti)*(Ei-Ti);
      float s12 = SQRTA(n1) + SQRTA(n2);
      mag += s12;
      if (c==3) lastpair = s12;
      float nr,ni; cmul(wr,wi,W128r,W128i,nr,ni); wr=nr; wi=ni;
    }
    if (tid==127) mag -= 0.5f*lastpair;   // k=512 is its own mirror
    if (tid==0){
      float2 Z0 = s_d[0];
      mag += fabsf(Z0.x+Z0.y) + fabsf(Z0.x-Z0.y);
    }
    mag *= 0.5f;
  }

  // ---- warp reductions for float stats (sync merged with phase-1 below) ----
  {
    u64 ssq;
    float a,b,sm0,sq0;
    UPK(smv,a,b); sm0 = a+b;
    UPK(sqv,a,b); sq0 = a+b;
    ssq = PK2(sm0, sq0);
    #pragma unroll
    for (int o=16;o;o>>=1){
      ssq  = ADDX(ssq, __shfl_xor_sync(0xffffffffu, ssq, o));
      mag += __shfl_xor_sync(0xffffffffu, mag, o);
    }
    unsigned kx = __reduce_max_sync(0xffffffffu, okey(mx));
    unsigned kn = __reduce_min_sync(0xffffffffu, okey(mn));
    if (lane==0){
      UPK(ssq,sm0,sq0);
      scr[warp]=sm0; scr[4+warp]=sq0; scr[8+warp]=mag;
      scr[12+warp]=okey_inv(kx); scr[16+warp]=okey_inv(kn);
    }
  }

  // ================= peak/valley: swizzled smem windows + shfl tail =================
  const int base  = tid<<4;
  const int base1 = base+1;
  float v[18];
  {
    const int sw = (tid>>1)&3;   // bank swizzle: kills 4-way conflicts on 64B lane stride
    #pragma unroll
    for (int c=0;c<4;c++){
      int cc = (c + sw) & 3;
      float4 q = *(const float4*)&s_sig[base + (cc<<2)];
      v[4*cc]=q.x; v[4*cc+1]=q.y; v[4*cc+2]=q.z; v[4*cc+3]=q.w;
    }
    float t0 = __shfl_down_sync(0xffffffffu, v[0], 1);
    float t1 = __shfl_down_sync(0xffffffffu, v[1], 1);
    if (lane==31){
      t0 = (base+16 < 2048) ? s_sig[base+16] : 0.f;
      t1 = (base+17 < 2048) ? s_sig[base+17] : 0.f;
    }
    v[16]=t0; v[17]=t1;
  }

  unsigned vm=0u;
  {
    unsigned pm=0u;
    bool cl[17], gl[17];
    #pragma unroll
    for (int j=0;j<17;j++){ cl[j] = v[j]<v[j+1]; gl[j] = v[j]>v[j+1]; }
    #pragma unroll
    for (int j=0;j<16;j++){
      if (cl[j] && gl[j+1]) pm |= (1u<<j);
      if (gl[j] && cl[j+1]) vm |= (1u<<j);
    }
    if (tid==127){ pm &= 0x3FFFu; vm &= 0x3FFFu; }
    int lnp = __reduce_add_sync(0xffffffffu, __popc(pm));
    int lnv = __reduce_add_sync(0xffffffffu, __popc(vm));
    int lp0 = __reduce_min_sync(0xffffffffu, pm ? base1 + (__ffs(pm)-1) : 0x7fffffff);
    int lv0 = __reduce_min_sync(0xffffffffu, vm ? base1 + (__ffs(vm)-1) : 0x7fffffff);
    int lvl = __reduce_max_sync(0xffffffffu, vm ? base1 + (31-__clz(vm)) : -1);
    if (lane==0){ iscr[warp]=lnp; iscr[4+warp]=lnv; iscr[8+warp]=lp0; iscr[12+warp]=lv0; iscr[16+warp]=lvl; }
  }
  __syncthreads();   // covers scr + iscr stores

  float sm_t=0.f, sq_t=0.f, mag_t=0.f, mx_t=-3.0e38f, mn_t=3.0e38f;
  if (tid==0){
    #pragma unroll
    for (int i=0;i<4;i++){
      sm_t+=scr[i]; sq_t+=scr[4+i]; mag_t+=scr[8+i];
      mx_t=fmaxf(mx_t,scr[12+i]); mn_t=fminf(mn_t,scr[16+i]);
    }
  }
  int np, nv, p0, v0, vlast;
  {
    int a = iscr[0]+iscr[1]+iscr[2]+iscr[3];
    int b = iscr[4]+iscr[5]+iscr[6]+iscr[7];
    int c2 = min(min(iscr[8],iscr[9]),  min(iscr[10],iscr[11]));
    int d  = min(min(iscr[12],iscr[13]),min(iscr[14],iscr[15]));
    int e  = max(max(iscr[16],iscr[17]),max(iscr[18],iscr[19]));
    np=a; nv=b;
    p0=(c2==0x7fffffff)?1:c2;
    v0=(d ==0x7fffffff)?1:d;
    vlast=(e<0)?2046:e;
  }
  const float half = 0.5f*(s_sig[p0] + s_sig[v0]);

  // Phase 2 (disjoint iscr[20..31]) + chunk prefix scan
  {
    unsigned hm=0u;
    #pragma unroll
    for (int j=0;j<16;j++) if (v[j+1]>=half) hm |= (1u<<j);

    unsigned wv = vm & wmask(v0+1, 2046, base1);
    unsigned wl = hm & wmask(v0, p0-1, base1);
    unsigned wrm = hm & wmask(v0+1, p0, base1);
    int lv1 = __reduce_min_sync(0xffffffffu, wv  ? base1 + (__ffs(wv)-1) : 0x7fffffff);
    int lli = __reduce_min_sync(0xffffffffu, wl  ? base1 + (__ffs(wl)-1) : 0x7fffffff);
    int lri = __reduce_max_sync(0xffffffffu, wrm ? base1 + (31-__clz(wrm)) : -1);
    if (lane==0){ iscr[20+warp]=lv1; iscr[24+warp]=lli; iscr[28+warp]=lri; }

    float ts = ((v[0]+v[1])+(v[2]+v[3])) + ((v[4]+v[5])+(v[6]+v[7]))
             + ((v[8]+v[9])+(v[10]+v[11])) + ((v[12]+v[13])+(v[14]+v[15]));
    float run = ts;
    #pragma unroll
    for (int o=1;o<32;o<<=1){
      float nb = __shfl_up_sync(0xffffffffu, run, o);
      if (lane>=o) run += nb;
    }
    if (lane==31) warptot[warp] = run;
    __syncthreads();
    float wb = 0.f;
    #pragma unroll
    for (int w=0;w<4;w++) if (w<warp) wb += warptot[w];
    chunkP[tid] = wb + run - ts;   // exclusive prefix: sum of s[0..base-1]
    if (tid==0){
      int a = min(min(iscr[20],iscr[21]),min(iscr[22],iscr[23]));
      int b = min(min(iscr[24],iscr[25]),min(iscr[26],iscr[27]));
      int c2= max(max(iscr[28],iscr[29]),max(iscr[30],iscr[31]));
      sh_v1=(a==0x7fffffff)?1:a;
      sh_li=(b==0x7fffffff)?v0:b;
      sh_ri=(c2<0)?p0:c2;
    }
  }
  __syncthreads();
  const int v1 = sh_v1;

  // P[i] (inclusive prefix) queries
  if (tid < 5){
    int i = v0;
    if      (tid==1) i = p0-2;
    else if (tid==2) i = p0;
    else if (tid==3) i = v1-2;
    else if (tid==4) i = vlast-2;
    if (i < 0) i = 0;
    float p = chunkP[i>>4];
    int b0 = i & ~15;
    #pragma unroll
    for (int t=0;t<16;t++){ if (b0+t<=i) p += s_sig[b0+t]; }
    qP[tid] = p;
  }
  __syncthreads();

  // ---- write 10 features ----
  if (tid==0){
    const int li = sh_li, ri = sh_ri;
    float Pv0=qP[0], Pp2=qP[1], Pp0=qP[2], Pv12=qP[3], Pvl2=qP[4];
    float sv0 = s_sig[v0], sp1 = s_sig[p0-1], sp0v = s_sig[p0];
    float sv11 = s_sig[v1-1], svl1 = s_sig[vlast-1];
    float A1r = (p0-2    >= v0) ? (0.5f*(sv0 + sp1)  + (Pp2  - Pv0)) : 0.f;
    float A2r = (v1-2    >= p0) ? (0.5f*(sp0v+ sv11) + (Pv12 - Pp0)) : 0.f;
    float PAr = (vlast-2 >= v0) ? (0.5f*(sv0 + svl1) + (Pvl2 - Pv0)) : 0.f;

    const float n = 2048.f;
    float var = (sq_t - sm_t*sm_t/n) / (n - 1.f);
    var = fmaxf(var, 0.f);
    float stdv = sqrtf(var);
    float mean_amp = (2.f*mag_t) / n;
    bool gate = (np>=1) && (nv>=2);
    float PA=0.f, A2=0.f, PH=0.f, A1=0.f, PW=0.f;
    if (gate){
      PA = PAr / 30.0f;
      A2 = A2r / 30.0f;
      A1 = A1r / 30.0f;
      PH = sp0v - sv0;
      PW = (float)(ri - li) / 30.0f;
    }
    float* o = out + row*10;
    o[0]=mx_t; o[1]=mx_t-mn_t; o[2]=var; o[3]=stdv; o[4]=mean_amp;
    o[5]=PA;   o[6]=A2;        o[7]=PH;  o[8]=A1;   o[9]=PW;
  }
}

extern "C" void kernel_launch(void* const* d_in, const int* in_sizes, int n_in,
                              void* d_out, int out_size) {
  const float* x = (const float*)d_in[0];
  float* out = (float*)d_out;
  (void)in_sizes; (void)n_in; (void)out_size;
  feat_kernel<<<32768, 128>>>(x, out);
}

// round 13
// speedup vs baseline: 1.0616x; 1.0616x over previous
#include <cuda_runtime.h>

#define PI_F 3.14159265358979323846f
typedef unsigned long long u64;

static __device__ __forceinline__ void cmul(float ar,float ai,float br,float bi,float&cr,float&ci){
  cr = ar*br - ai*bi; ci = ar*bi + ai*br;
}

// ---- f32x2 packed helpers ----
static __device__ __forceinline__ u64 PK2(float lo, float hi){
  u64 r; asm("mov.b64 %0,{%1,%2};":"=l"(r):"f"(lo),"f"(hi)); return r;
}
static __device__ __forceinline__ void UPK(u64 v, float&lo, float&hi){
  asm("mov.b64 {%0,%1},%2;":"=f"(lo),"=f"(hi):"l"(v));
}
static __device__ __forceinline__ u64 SWP(u64 v){
  u64 r; asm("{\n\t.reg .b32 a,b;\n\tmov.b64 {a,b},%1;\n\tmov.b64 %0,{b,a};\n\t}":"=l"(r):"l"(v)); return r;
}
static __device__ __forceinline__ u64 ADDX(u64 a,u64 b){
  u64 r; asm("add.rn.f32x2 %0,%1,%2;":"=l"(r):"l"(a),"l"(b)); return r;
}
static __device__ __forceinline__ u64 MULX(u64 a,u64 b){
  u64 r; asm("mul.rn.f32x2 %0,%1,%2;":"=l"(r):"l"(a),"l"(b)); return r;
}
static __device__ __forceinline__ u64 FMX(u64 a,u64 b,u64 c){
  u64 r; asm("fma.rn.f32x2 %0,%1,%2,%3;":"=l"(r):"l"(a),"l"(b),"l"(c)); return r;
}
static __device__ __forceinline__ float SQRTA(float x){
  float r; asm("sqrt.approx.f32 %0,%1;":"=f"(r):"f"(x)); return r;
}

#define C_NEG1 0xBF800000BF800000ULL  /* (-1,-1) */
#define C_P1M1 0xBF8000003F800000ULL  /* (+1,-1) */
#define C_M1P1 0x3F800000BF800000ULL  /* (-1,+1) */
#define C_CC   0x3F3504F33F3504F3ULL  /* ( C, C) */
#define C_CMC  0xBF3504F33F3504F3ULL  /* ( C,-C) */

// packed DFT-8
static __device__ __forceinline__ void dft8p(u64 x[8]){
  u64 u0=ADDX(x[0],x[4]), u1=FMX(x[4],C_NEG1,x[0]);
  u64 u2=ADDX(x[2],x[6]), u3=FMX(x[6],C_NEG1,x[2]);
  u64 v0=ADDX(x[1],x[5]), v1=FMX(x[5],C_NEG1,x[1]);
  u64 v2=ADDX(x[3],x[7]), v3=FMX(x[7],C_NEG1,x[3]);
  u64 E0=ADDX(u0,u2),     E2=FMX(u2,C_NEG1,u0);
  u64 su3=SWP(u3);
  u64 E1=FMX(su3,C_P1M1,u1), E3=FMX(su3,C_M1P1,u1);
  u64 O0=ADDX(v0,v2),     O2=FMX(v2,C_NEG1,v0);
  u64 sv3=SWP(v3);
  u64 O1=FMX(sv3,C_P1M1,v1), O3=FMX(sv3,C_M1P1,v1);
  u64 t1=FMX(SWP(O1),C_P1M1,O1);
  u64 w1=MULX(t1,C_CC);
  u64 sO2=SWP(O2);
  u64 t3=FMX(O3,C_M1P1,SWP(O3));
  u64 w3=MULX(t3,C_CMC);
  x[0]=ADDX(E0,O0);  x[4]=FMX(O0,C_NEG1,E0);
  x[1]=ADDX(E1,w1);  x[5]=FMX(w1,C_NEG1,E1);
  x[2]=FMX(sO2,C_P1M1,E2); x[6]=FMX(sO2,C_M1P1,E2);
  x[3]=ADDX(E3,w3);  x[7]=FMX(w3,C_NEG1,E3);
}

// swizzled slot for frequency k (conflict-free writes and consecutive-k reads)
static __device__ __forceinline__ int sig_idx(int k){
  return (k & ~7) | ((k + (k>>3)) & 7);
}

// bits j (0..15) with lo <= base1+j <= hi
static __device__ __forceinline__ unsigned wmask(int lo, int hi, int base1){
  int jlo = lo - base1, jhi = hi - base1;
  jlo = max(jlo, 0); jhi = min(jhi, 15);
  if (jhi < jlo) return 0u;
  return (0xFFFFu << jlo) & (0xFFFFu >> (15 - jhi));
}

// order-preserving float<->uint key (no NaNs in data)
static __device__ __forceinline__ unsigned okey(float x){
  unsigned u = __float_as_uint(x);
  return u ^ ((unsigned)(((int)u)>>31) | 0x80000000u);
}
static __device__ __forceinline__ float okey_inv(unsigned k){
  unsigned u = (k & 0x80000000u) ? (k ^ 0x80000000u) : ~k;
  return __uint_as_float(u);
}

__global__ void __launch_bounds__(128, 9)
feat_kernel(const float* __restrict__ x, float* __restrict__ out)
{
  __shared__ __align__(16) float2 s_d[1088];  // passes 1-2: pad i+(i>>4); final: sigma(k)
  __shared__ float scr[20];
  __shared__ float chunkP[128];
  __shared__ float warptot[4];
  __shared__ float qP[5];
  __shared__ int   iscr[32];   // phase1: [0..19], phase2: [20..31]
  __shared__ int   sh_v1, sh_li, sh_ri;

  const int tid  = threadIdx.x;   // 0..127
  const int lane = tid & 31;
  const int warp = tid >> 5;
  const size_t row = blockIdx.x;
  const float* xp = x + row * 2048;

  // ============ 1024-pt complex FFT of z_n = x[2n] + i x[2n+1], DIF 8,8,8,2 ============
  u64 X[8];
  float mx=-3.0e38f, mn=3.0e38f;
  u64 smv=0ULL, sqv=0ULL;

  // ---- pass 1: LDG.64 at FFT stride (row stays hot in L1; no smem mirror) ----
  {
    const u64* zin = (const u64*)xp;
    #pragma unroll
    for (int m=0;m<8;m++){
      u64 z = zin[tid + (m<<7)];
      float zx,zy; UPK(z,zx,zy);
      mx=fmaxf(mx,fmaxf(zx,zy)); mn=fminf(mn,fminf(zx,zy));
      smv = ADDX(smv, z);
      sqv = FMX(z, z, sqv);
      X[m] = z;
    }
    dft8p(X);
    float sn,cs; __sincosf(-2.f*PI_F*(float)tid*(1.f/1024.f), &sn, &cs);
    const int ob = tid + (tid>>4);
    *(u64*)&s_d[ob] = X[0];
    float wr=cs, wi=sn;
    #pragma unroll
    for (int q=1;q<8;q++){
      float xr,xi; UPK(X[q],xr,xi);
      float rr,ii; cmul(xr,xi,wr,wi,rr,ii);
      s_d[ob + 136*q] = make_float2(rr,ii);
      float nr,ni; cmul(wr,wi,cs,sn,nr,ni); wr=nr; wi=ni;
    }
  }
  __syncthreads();

  // ---- pass 2 ----
  {
    const int sub = tid>>4, tt = tid&15;
    const int ob = 136*sub + tt;
    #pragma unroll
    for (int m=0;m<8;m++) X[m] = *(const u64*)&s_d[ob + 17*m];
    dft8p(X);
    float sn,cs; __sincosf(-2.f*PI_F*(float)tt*(1.f/128.f), &sn, &cs);
    float wr=cs, wi=sn;
    *(u64*)&s_d[ob] = X[0];
    #pragma unroll
    for (int q=1;q<8;q++){
      float xr,xi; UPK(X[q],xr,xi);
      float rr,ii; cmul(xr,xi,wr,wi,rr,ii);
      s_d[ob + 17*q] = make_float2(rr,ii);
      float nr,ni; cmul(wr,wi,cs,sn,nr,ni); wr=nr; wi=ni;
    }
  }
  __syncthreads();

  // ---- pass 3 + radix-2 (shuffle partner tid^16); compile-time W16^q ----
  {
    const int tt  = (tid>>4)&1;
    const int sid = (tid&15) | ((tid>>5)<<4);   // 0..63
    const int ob  = 17*sid + tt;
    #pragma unroll
    for (int m=0;m<8;m++) X[m] = *(const u64*)&s_d[ob + 2*m];
    dft8p(X);
    if (tt){
      const float WR[8] = {1.f,  0.92387953251128675613f,  0.70710678118654752440f,
                            0.38268343236508977173f, 0.f, -0.38268343236508977173f,
                           -0.70710678118654752440f, -0.92387953251128675613f};
      const float WI[8] = {0.f, -0.38268343236508977173f, -0.70710678118654752440f,
                           -0.92387953251128675613f, -1.f, -0.92387953251128675613f,
                           -0.70710678118654752440f, -0.38268343236508977173f};
      #pragma unroll
      for (int q=1;q<8;q++){
        float xr,xi; UPK(X[q],xr,xi);
        X[q] = PK2(xr*WR[q] - xi*WI[q], xr*WI[q] + xi*WR[q]);
      }
    }
    u64 Y[8];
    #pragma unroll
    for (int q=0;q<8;q++){
      u64 other = __shfl_xor_sync(0xffffffffu, X[q], 16);
      Y[q] = tt ? FMX(X[q], C_NEG1, other)   // A - B
                : ADDX(X[q], other);         // A + B
    }
    __syncthreads();   // pass-3 reads done before sigma-layout overwrite
    const int e = sid & 7, f = sid >> 3;
    const int s0 = (e<<3) | ((f+e)&7) | (tt<<9);
    #pragma unroll
    for (int q=0;q<8;q++) *(u64*)&s_d[s0 + (q<<6)] = Y[q];
  }
  __syncthreads();

  // ---- unpack real-FFT magnitudes (scalar, constant-step chain) ----
  float mag = 0.f;
  {
    const float W128r =  0.92387953251128675613f;
    const float W128i = -0.38268343236508977173f;
    int k0 = 1 + tid;
    float wr, wi; __sincosf(-PI_F*(float)k0*(1.f/1024.f), &wi, &wr);
    float lastpair = 0.f;
    #pragma unroll
    for (int c=0;c<4;c++){
      int k  = k0 + (c<<7);
      int k2 = 1024 - k;
      float2 Z1 = s_d[sig_idx(k)];
      float2 Z2 = s_d[sig_idx(k2)];
      float Er = Z1.x + Z2.x;
      float Ei = Z1.y - Z2.y;
      float Or = Z1.y + Z2.y;
      float Oi = Z2.x - Z1.x;
      float Tr = wr*Or - wi*Oi;
      float Ti = wr*Oi + wi*Or;
      float n1 = (Er+Tr)*(Er+Tr) + (Ei+Ti)*(Ei+Ti);
      float n2 = (Er-Tr)*(Er-Tr) + (Ei-Ti)*(Ei-Ti);
      float s12 = SQRTA(n1) + SQRTA(n2);
      mag += s12;
      if (c==3) lastpair = s12;
      float nr,ni; cmul(wr,wi,W128r,W128i,nr,ni); wr=nr; wi=ni;
    }
    if (tid==127) mag -= 0.5f*lastpair;   // k=512 is its own mirror
    if (tid==0){
      float2 Z0 = s_d[0];
      mag += fabsf(Z0.x+Z0.y) + fabsf(Z0.x-Z0.y);
    }
    mag *= 0.5f;
  }

  // ---- warp reductions for float stats (sync merged with phase-1 below) ----
  {
    u64 ssq;
    float a,b,sm0,sq0;
    UPK(smv,a,b); sm0 = a+b;
    UPK(sqv,a,b); sq0 = a+b;
    ssq = PK2(sm0, sq0);
    #pragma unroll
    for (int o=16;o;o>>=1){
      ssq  = ADDX(ssq, __shfl_xor_sync(0xffffffffu, ssq, o));
      mag += __shfl_xor_sync(0xffffffffu, mag, o);
    }
    unsigned kx = __reduce_max_sync(0xffffffffu, okey(mx));
    unsigned kn = __reduce_min_sync(0xffffffffu, okey(mn));
    if (lane==0){
      UPK(ssq,sm0,sq0);
      scr[warp]=sm0; scr[4+warp]=sq0; scr[8+warp]=mag;
      scr[12+warp]=okey_inv(kx); scr[16+warp]=okey_inv(kn);
    }
  }

  // ================= peak/valley: global loads + shfl tail (no strided scalars) =================
  const int base  = tid<<4;
  const int base1 = base+1;
  float v[18];
  {
    const float4* xv4 = (const float4*)(xp + base);
    #pragma unroll
    for (int c=0;c<4;c++){
      float4 q = xv4[c];
      v[4*c]=q.x; v[4*c+1]=q.y; v[4*c+2]=q.z; v[4*c+3]=q.w;
    }
    // s[base+16], s[base+17] are the NEXT thread's v[0], v[1]
    float t0 = __shfl_down_sync(0xffffffffu, v[0], 1);
    float t1 = __shfl_down_sync(0xffffffffu, v[1], 1);
    if (lane==31){
      t0 = (base+16 < 2048) ? xp[base+16] : 0.f;
      t1 = (base+17 < 2048) ? xp[base+17] : 0.f;
    }
    v[16]=t0; v[17]=t1;
  }

  unsigned vm=0u;
  {
    unsigned pm=0u;
    bool cl[17], gl[17];
    #pragma unroll
    for (int j=0;j<17;j++){ cl[j] = v[j]<v[j+1]; gl[j] = v[j]>v[j+1]; }
    #pragma unroll
    for (int j=0;j<16;j++){
      if (cl[j] && gl[j+1]) pm |= (1u<<j);
      if (gl[j] && cl[j+1]) vm |= (1u<<j);
    }
    if (tid==127){ pm &= 0x3FFFu; vm &= 0x3FFFu; }
    int lnp = __reduce_add_sync(0xffffffffu, __popc(pm));
    int lnv = __reduce_add_sync(0xffffffffu, __popc(vm));
    int lp0 = __reduce_min_sync(0xffffffffu, pm ? base1 + (__ffs(pm)-1) : 0x7fffffff);
    int lv0 = __reduce_min_sync(0xffffffffu, vm ? base1 + (__ffs(vm)-1) : 0x7fffffff);
    int lvl = __reduce_max_sync(0xffffffffu, vm ? base1 + (31-__clz(vm)) : -1);
    if (lane==0){ iscr[warp]=lnp; iscr[4+warp]=lnv; iscr[8+warp]=lp0; iscr[12+warp]=lv0; iscr[16+warp]=lvl; }
  }
  __syncthreads();   // covers scr + iscr stores

  float sm_t=0.f, sq_t=0.f, mag_t=0.f, mx_t=-3.0e38f, mn_t=3.0e38f;
  if (tid==0){
    #pragma unroll
    for (int i=0;i<4;i++){
      sm_t+=scr[i]; sq_t+=scr[4+i]; mag_t+=scr[8+i];
      mx_t=fmaxf(mx_t,scr[12+i]); mn_t=fminf(mn_t,scr[16+i]);
    }
  }
  int np, nv, p0, v0, vlast;
  {
    int a = iscr[0]+iscr[1]+iscr[2]+iscr[3];
    int b = iscr[4]+iscr[5]+iscr[6]+iscr[7];
    int c2 = min(min(iscr[8],iscr[9]),  min(iscr[10],iscr[11]));
    int d  = min(min(iscr[12],iscr[13]),min(iscr[14],iscr[15]));
    int e  = max(max(iscr[16],iscr[17]),max(iscr[18],iscr[19]));
    np=a; nv=b;
    p0=(c2==0x7fffffff)?1:c2;
    v0=(d ==0x7fffffff)?1:d;
    vlast=(e<0)?2046:e;
  }
  const float half = 0.5f*(xp[p0] + xp[v0]);

  // Phase 2 (disjoint iscr[20..31]) + chunk prefix scan
  {
    unsigned hm=0u;
    #pragma unroll
    for (int j=0;j<16;j++) if (v[j+1]>=half) hm |= (1u<<j);

    unsigned wv = vm & wmask(v0+1, 2046, base1);
    unsigned wl = hm & wmask(v0, p0-1, base1);
    unsigned wrm = hm & wmask(v0+1, p0, base1);
    int lv1 = __reduce_min_sync(0xffffffffu, wv  ? base1 + (__ffs(wv)-1) : 0x7fffffff);
    int lli = __reduce_min_sync(0xffffffffu, wl  ? base1 + (__ffs(wl)-1) : 0x7fffffff);
    int lri = __reduce_max_sync(0xffffffffu, wrm ? base1 + (31-__clz(wrm)) : -1);
    if (lane==0){ iscr[20+warp]=lv1; iscr[24+warp]=lli; iscr[28+warp]=lri; }

    float ts = ((v[0]+v[1])+(v[2]+v[3])) + ((v[4]+v[5])+(v[6]+v[7]))
             + ((v[8]+v[9])+(v[10]+v[11])) + ((v[12]+v[13])+(v[14]+v[15]));
    float run = ts;
    #pragma unroll
    for (int o=1;o<32;o<<=1){
      float nb = __shfl_up_sync(0xffffffffu, run, o);
      if (lane>=o) run += nb;
    }
    if (lane==31) warptot[warp] = run;
    __syncthreads();
    float wb = 0.f;
    #pragma unroll
    for (int w=0;w<4;w++) if (w<warp) wb += warptot[w];
    chunkP[tid] = wb + run - ts;   // exclusive prefix: sum of s[0..base-1]
    if (tid==0){
      int a = min(min(iscr[20],iscr[21]),min(iscr[22],iscr[23]));
      int b = min(min(iscr[24],iscr[25]),min(iscr[26],iscr[27]));
      int c2= max(max(iscr[28],iscr[29]),max(iscr[30],iscr[31]));
      sh_v1=(a==0x7fffffff)?1:a;
      sh_li=(b==0x7fffffff)?v0:b;
      sh_ri=(c2<0)?p0:c2;
    }
  }
  __syncthreads();
  const int v1 = sh_v1;

  // P[i] (inclusive prefix) queries
  if (tid < 5){
    int i = v0;
    if      (tid==1) i = p0-2;
    else if (tid==2) i = p0;
    else if (tid==3) i = v1-2;
    else if (tid==4) i = vlast-2;
    if (i < 0) i = 0;
    float p = chunkP[i>>4];
    int b0 = i & ~15;
    #pragma unroll
    for (int t=0;t<16;t++){ if (b0+t<=i) p += xp[b0+t]; }
    qP[tid] = p;
  }
  __syncthreads();

  // ---- write 10 features ----
  if (tid==0){
    const int li = sh_li, ri = sh_ri;
    float Pv0=qP[0], Pp2=qP[1], Pp0=qP[2], Pv12=qP[3], Pvl2=qP[4];
    float sv0 = xp[v0], sp1 = xp[p0-1], sp0v = xp[p0];
    float sv11 = xp[v1-1], svl1 = xp[vlast-1];
    float A1r = (p0-2    >= v0) ? (0.5f*(sv0 + sp1)  + (Pp2  - Pv0)) : 0.f;
    float A2r = (v1-2    >= p0) ? (0.5f*(sp0v+ sv11) + (Pv12 - Pp0)) : 0.f;
    float PAr = (vlast-2 >= v0) ? (0.5f*(sv0 + svl1) + (Pvl2 - Pv0)) : 0.f;

    const float n = 2048.f;
    float var = (sq_t - sm_t*sm_t/n) / (n - 1.f);
    var = fmaxf(var, 0.f);
    float stdv = sqrtf(var);
    float mean_amp = (2.f*mag_t) / n;
    bool gate = (np>=1) && (nv>=2);
    float PA=0.f, A2=0.f, PH=0.f, A1=0.f, PW=0.f;
    if (gate){
      PA = PAr / 30.0f;
      A2 = A2r / 30.0f;
      A1 = A1r / 30.0f;
      PH = sp0v - sv0;
      PW = (float)(ri - li) / 30.0f;
    }
    float* o = out + row*10;
    o[0]=mx_t; o[1]=mx_t-mn_t; o[2]=var; o[3]=stdv; o[4]=mean_amp;
    o[5]=PA;   o[6]=A2;        o[7]=PH;  o[8]=A1;   o[9]=PW;
  }
}

extern "C" void kernel_launch(void* const* d_in, const int* in_sizes, int n_in,
                              void* d_out, int out_size) {
  const float* x = (const float*)d_in[0];
  float* out = (float*)d_out;
  (void)in_sizes; (void)n_in; (void)out_size;
  feat_kernel<<<32768, 128>>>(x, out);
}

// round 14
// speedup vs baseline: 1.0847x; 1.0218x over previous
#include <cuda_runtime.h>

#define PI_F 3.14159265358979323846f
typedef unsigned long long u64;

static __device__ __forceinline__ void cmul(float ar,float ai,float br,float bi,float&cr,float&ci){
  cr = ar*br - ai*bi; ci = ar*bi + ai*br;
}

// ---- f32x2 packed helpers ----
static __device__ __forceinline__ u64 PK2(float lo, float hi){
  u64 r; asm("mov.b64 %0,{%1,%2};":"=l"(r):"f"(lo),"f"(hi)); return r;
}
static __device__ __forceinline__ void UPK(u64 v, float&lo, float&hi){
  asm("mov.b64 {%0,%1},%2;":"=f"(lo),"=f"(hi):"l"(v));
}
static __device__ __forceinline__ u64 SWP(u64 v){
  u64 r; asm("{\n\t.reg .b32 a,b;\n\tmov.b64 {a,b},%1;\n\tmov.b64 %0,{b,a};\n\t}":"=l"(r):"l"(v)); return r;
}
static __device__ __forceinline__ u64 ADDX(u64 a,u64 b){
  u64 r; asm("add.rn.f32x2 %0,%1,%2;":"=l"(r):"l"(a),"l"(b)); return r;
}
static __device__ __forceinline__ u64 MULX(u64 a,u64 b){
  u64 r; asm("mul.rn.f32x2 %0,%1,%2;":"=l"(r):"l"(a),"l"(b)); return r;
}
static __device__ __forceinline__ u64 FMX(u64 a,u64 b,u64 c){
  u64 r; asm("fma.rn.f32x2 %0,%1,%2,%3;":"=l"(r):"l"(a),"l"(b),"l"(c)); return r;
}
static __device__ __forceinline__ float SQRTA(float x){
  float r; asm("sqrt.approx.f32 %0,%1;":"=f"(r):"f"(x)); return r;
}

#define C_NEG1 0xBF800000BF800000ULL  /* (-1,-1) */
#define C_P1M1 0xBF8000003F800000ULL  /* (+1,-1) */
#define C_M1P1 0x3F800000BF800000ULL  /* (-1,+1) */
#define C_CC   0x3F3504F33F3504F3ULL  /* ( C, C) */
#define C_CMC  0xBF3504F33F3504F3ULL  /* ( C,-C) */

// packed DFT-8
static __device__ __forceinline__ void dft8p(u64 x[8]){
  u64 u0=ADDX(x[0],x[4]), u1=FMX(x[4],C_NEG1,x[0]);
  u64 u2=ADDX(x[2],x[6]), u3=FMX(x[6],C_NEG1,x[2]);
  u64 v0=ADDX(x[1],x[5]), v1=FMX(x[5],C_NEG1,x[1]);
  u64 v2=ADDX(x[3],x[7]), v3=FMX(x[7],C_NEG1,x[3]);
  u64 E0=ADDX(u0,u2),     E2=FMX(u2,C_NEG1,u0);
  u64 su3=SWP(u3);
  u64 E1=FMX(su3,C_P1M1,u1), E3=FMX(su3,C_M1P1,u1);
  u64 O0=ADDX(v0,v2),     O2=FMX(v2,C_NEG1,v0);
  u64 sv3=SWP(v3);
  u64 O1=FMX(sv3,C_P1M1,v1), O3=FMX(sv3,C_M1P1,v1);
  u64 t1=FMX(SWP(O1),C_P1M1,O1);
  u64 w1=MULX(t1,C_CC);
  u64 sO2=SWP(O2);
  u64 t3=FMX(O3,C_M1P1,SWP(O3));
  u64 w3=MULX(t3,C_CMC);
  x[0]=ADDX(E0,O0);  x[4]=FMX(O0,C_NEG1,E0);
  x[1]=ADDX(E1,w1);  x[5]=FMX(w1,C_NEG1,E1);
  x[2]=FMX(sO2,C_P1M1,E2); x[6]=FMX(sO2,C_M1P1,E2);
  x[3]=ADDX(E3,w3);  x[7]=FMX(w3,C_NEG1,E3);
}

// swizzled slot for frequency k (conflict-free writes and consecutive-k reads)
static __device__ __forceinline__ int sig_idx(int k){
  return (k & ~7) | ((k + (k>>3)) & 7);
}

// bits j (0..15) with lo <= base1+j <= hi
static __device__ __forceinline__ unsigned wmask(int lo, int hi, int base1){
  int jlo = lo - base1, jhi = hi - base1;
  jlo = max(jlo, 0); jhi = min(jhi, 15);
  if (jhi < jlo) return 0u;
  return (0xFFFFu << jlo) & (0xFFFFu >> (15 - jhi));
}

// order-preserving float<->uint key (no NaNs in data)
static __device__ __forceinline__ unsigned okey(float x){
  unsigned u = __float_as_uint(x);
  return u ^ ((unsigned)(((int)u)>>31) | 0x80000000u);
}
static __device__ __forceinline__ float okey_inv(unsigned k){
  unsigned u = (k & 0x80000000u) ? (k ^ 0x80000000u) : ~k;
  return __uint_as_float(u);
}

__global__ void __launch_bounds__(128, 10)
feat_kernel(const float* __restrict__ x, float* __restrict__ out)
{
  __shared__ __align__(16) float2 s_d[1088];   // passes 1-2 (pad i+(i>>4))
  __shared__ __align__(16) float2 s_d2[1024];  // final sigma(k) layout (double buffer)
  __shared__ float scr[20];
  __shared__ float chunkP[128];
  __shared__ float warptot[4];
  __shared__ float qP[5];
  __shared__ int   iscr[32];   // phase1: [0..19], phase2: [20..31]
  __shared__ int   sh_v1, sh_li, sh_ri;

  const int tid  = threadIdx.x;   // 0..127
  const int lane = tid & 31;
  const int warp = tid >> 5;
  const size_t row = blockIdx.x;
  const float* xp = x + row * 2048;

  // ============ 1024-pt complex FFT of z_n = x[2n] + i x[2n+1], DIF 8,8,8,2 ============
  u64 X[8];
  float mx=-3.0e38f, mn=3.0e38f;
  u64 smv=0ULL, sqv=0ULL;

  // ---- pass 1: LDG.64 at FFT stride (row stays hot in L1) ----
  {
    const u64* zin = (const u64*)xp;
    #pragma unroll
    for (int m=0;m<8;m++){
      u64 z = zin[tid + (m<<7)];
      float zx,zy; UPK(z,zx,zy);
      mx=fmaxf(mx,fmaxf(zx,zy)); mn=fminf(mn,fminf(zx,zy));
      smv = ADDX(smv, z);
      sqv = FMX(z, z, sqv);
      X[m] = z;
    }
    dft8p(X);
    float sn,cs; __sincosf(-2.f*PI_F*(float)tid*(1.f/1024.f), &sn, &cs);
    const int ob = tid + (tid>>4);
    *(u64*)&s_d[ob] = X[0];
    float wr=cs, wi=sn;
    #pragma unroll
    for (int q=1;q<8;q++){
      float xr,xi; UPK(X[q],xr,xi);
      float rr,ii; cmul(xr,xi,wr,wi,rr,ii);
      s_d[ob + 136*q] = make_float2(rr,ii);
      float nr,ni; cmul(wr,wi,cs,sn,nr,ni); wr=nr; wi=ni;
    }
  }
  __syncthreads();

  // ---- pass 2 ----
  {
    const int sub = tid>>4, tt = tid&15;
    const int ob = 136*sub + tt;
    #pragma unroll
    for (int m=0;m<8;m++) X[m] = *(const u64*)&s_d[ob + 17*m];
    dft8p(X);
    float sn,cs; __sincosf(-2.f*PI_F*(float)tt*(1.f/128.f), &sn, &cs);
    float wr=cs, wi=sn;
    *(u64*)&s_d[ob] = X[0];
    #pragma unroll
    for (int q=1;q<8;q++){
      float xr,xi; UPK(X[q],xr,xi);
      float rr,ii; cmul(xr,xi,wr,wi,rr,ii);
      s_d[ob + 17*q] = make_float2(rr,ii);
      float nr,ni; cmul(wr,wi,cs,sn,nr,ni); wr=nr; wi=ni;
    }
  }
  __syncthreads();

  // ---- pass 3 + radix-2 (shuffle partner tid^16); writes DOUBLE BUFFER -> no mid sync ----
  {
    const int tt  = (tid>>4)&1;
    const int sid = (tid&15) | ((tid>>5)<<4);   // 0..63
    const int ob  = 17*sid + tt;
    #pragma unroll
    for (int m=0;m<8;m++) X[m] = *(const u64*)&s_d[ob + 2*m];
    dft8p(X);
    if (tt){
      const float WR[8] = {1.f,  0.92387953251128675613f,  0.70710678118654752440f,
                            0.38268343236508977173f, 0.f, -0.38268343236508977173f,
                           -0.70710678118654752440f, -0.92387953251128675613f};
      const float WI[8] = {0.f, -0.38268343236508977173f, -0.70710678118654752440f,
                           -0.92387953251128675613f, -1.f, -0.92387953251128675613f,
                           -0.70710678118654752440f, -0.38268343236508977173f};
      #pragma unroll
      for (int q=1;q<8;q++){
        float xr,xi; UPK(X[q],xr,xi);
        X[q] = PK2(xr*WR[q] - xi*WI[q], xr*WI[q] + xi*WR[q]);
      }
    }
    const int e = sid & 7, f = sid >> 3;
    const int s0 = (e<<3) | ((f+e)&7) | (tt<<9);
    #pragma unroll
    for (int q=0;q<8;q++){
      u64 other = __shfl_xor_sync(0xffffffffu, X[q], 16);
      u64 y = tt ? FMX(X[q], C_NEG1, other)   // A - B
                 : ADDX(X[q], other);         // A + B
      *(u64*)&s_d2[s0 + (q<<6)] = y;
    }
  }
  __syncthreads();

  // ---- unpack real-FFT magnitudes (reads s_d2) ----
  float mag = 0.f;
  {
    const float W128r =  0.92387953251128675613f;
    const float W128i = -0.38268343236508977173f;
    int k0 = 1 + tid;
    float wr, wi; __sincosf(-PI_F*(float)k0*(1.f/1024.f), &wi, &wr);
    float lastpair = 0.f;
    #pragma unroll
    for (int c=0;c<4;c++){
      int k  = k0 + (c<<7);
      int k2 = 1024 - k;
      float2 Z1 = s_d2[sig_idx(k)];
      float2 Z2 = s_d2[sig_idx(k2)];
      float Er = Z1.x + Z2.x;
      float Ei = Z1.y - Z2.y;
      float Or = Z1.y + Z2.y;
      float Oi = Z2.x - Z1.x;
      float Tr = wr*Or - wi*Oi;
      float Ti = wr*Oi + wi*Or;
      float n1 = (Er+Tr)*(Er+Tr) + (Ei+Ti)*(Ei+Ti);
      float n2 = (Er-Tr)*(Er-Tr) + (Ei-Ti)*(Ei-Ti);
      float s12 = SQRTA(n1) + SQRTA(n2);
      mag += s12;
      if (c==3) lastpair = s12;
      float nr,ni; cmul(wr,wi,W128r,W128i,nr,ni); wr=nr; wi=ni;
    }
    if (tid==127) mag -= 0.5f*lastpair;   // k=512 is its own mirror
    if (tid==0){
      float2 Z0 = s_d2[0];
      mag += fabsf(Z0.x+Z0.y) + fabsf(Z0.x-Z0.y);
    }
    mag *= 0.5f;
  }

  // ---- warp reductions for float stats (sync merged with phase-1 below) ----
  {
    u64 ssq;
    float a,b,sm0,sq0;
    UPK(smv,a,b); sm0 = a+b;
    UPK(sqv,a,b); sq0 = a+b;
    ssq = PK2(sm0, sq0);
    #pragma unroll
    for (int o=16;o;o>>=1){
      ssq  = ADDX(ssq, __shfl_xor_sync(0xffffffffu, ssq, o));
      mag += __shfl_xor_sync(0xffffffffu, mag, o);
    }
    unsigned kx = __reduce_max_sync(0xffffffffu, okey(mx));
    unsigned kn = __reduce_min_sync(0xffffffffu, okey(mn));
    if (lane==0){
      UPK(ssq,sm0,sq0);
      scr[warp]=sm0; scr[4+warp]=sq0; scr[8+warp]=mag;
      scr[12+warp]=okey_inv(kx); scr[16+warp]=okey_inv(kn);
    }
  }

  // ================= peak/valley: global loads + shfl tail =================
  const int base  = tid<<4;
  const int base1 = base+1;
  float v[18];
  {
    const float4* xv4 = (const float4*)(xp + base);
    #pragma unroll
    for (int c=0;c<4;c++){
      float4 q = xv4[c];
      v[4*c]=q.x; v[4*c+1]=q.y; v[4*c+2]=q.z; v[4*c+3]=q.w;
    }
    float t0 = __shfl_down_sync(0xffffffffu, v[0], 1);
    float t1 = __shfl_down_sync(0xffffffffu, v[1], 1);
    if (lane==31){
      t0 = (base+16 < 2048) ? xp[base+16] : 0.f;
      t1 = (base+17 < 2048) ? xp[base+17] : 0.f;
    }
    v[16]=t0; v[17]=t1;
  }

  unsigned vm=0u;
  {
    unsigned pm=0u;
    bool cl[17], gl[17];
    #pragma unroll
    for (int j=0;j<17;j++){ cl[j] = v[j]<v[j+1]; gl[j] = v[j]>v[j+1]; }
    #pragma unroll
    for (int j=0;j<16;j++){
      if (cl[j] && gl[j+1]) pm |= (1u<<j);
      if (gl[j] && cl[j+1]) vm |= (1u<<j);
    }
    if (tid==127){ pm &= 0x3FFFu; vm &= 0x3FFFu; }
    int lnp = __reduce_add_sync(0xffffffffu, __popc(pm));
    int lnv = __reduce_add_sync(0xffffffffu, __popc(vm));
    int lp0 = __reduce_min_sync(0xffffffffu, pm ? base1 + (__ffs(pm)-1) : 0x7fffffff);
    int lv0 = __reduce_min_sync(0xffffffffu, vm ? base1 + (__ffs(vm)-1) : 0x7fffffff);
    int lvl = __reduce_max_sync(0xffffffffu, vm ? base1 + (31-__clz(vm)) : -1);
    if (lane==0){ iscr[warp]=lnp; iscr[4+warp]=lnv; iscr[8+warp]=lp0; iscr[12+warp]=lv0; iscr[16+warp]=lvl; }
  }
  __syncthreads();   // covers scr + iscr stores

  float sm_t=0.f, sq_t=0.f, mag_t=0.f, mx_t=-3.0e38f, mn_t=3.0e38f;
  if (tid==0){
    #pragma unroll
    for (int i=0;i<4;i++){
      sm_t+=scr[i]; sq_t+=scr[4+i]; mag_t+=scr[8+i];
      mx_t=fmaxf(mx_t,scr[12+i]); mn_t=fminf(mn_t,scr[16+i]);
    }
  }
  int np, nv, p0, v0, vlast;
  {
    int a = iscr[0]+iscr[1]+iscr[2]+iscr[3];
    int b = iscr[4]+iscr[5]+iscr[6]+iscr[7];
    int c2 = min(min(iscr[8],iscr[9]),  min(iscr[10],iscr[11]));
    int d  = min(min(iscr[12],iscr[13]),min(iscr[14],iscr[15]));
    int e  = max(max(iscr[16],iscr[17]),max(iscr[18],iscr[19]));
    np=a; nv=b;
    p0=(c2==0x7fffffff)?1:c2;
    v0=(d ==0x7fffffff)?1:d;
    vlast=(e<0)?2046:e;
  }
  const float half = 0.5f*(xp[p0] + xp[v0]);

  // Phase 2 (disjoint iscr[20..31]) + chunk prefix scan
  {
    unsigned hm=0u;
    #pragma unroll
    for (int j=0;j<16;j++) if (v[j+1]>=half) hm |= (1u<<j);

    unsigned wv = vm & wmask(v0+1, 2046, base1);
    unsigned wl = hm & wmask(v0, p0-1, base1);
    unsigned wrm = hm & wmask(v0+1, p0, base1);
    int lv1 = __reduce_min_sync(0xffffffffu, wv  ? base1 + (__ffs(wv)-1) : 0x7fffffff);
    int lli = __reduce_min_sync(0xffffffffu, wl  ? base1 + (__ffs(wl)-1) : 0x7fffffff);
    int lri = __reduce_max_sync(0xffffffffu, wrm ? base1 + (31-__clz(wrm)) : -1);
    if (lane==0){ iscr[20+warp]=lv1; iscr[24+warp]=lli; iscr[28+warp]=lri; }

    float ts = ((v[0]+v[1])+(v[2]+v[3])) + ((v[4]+v[5])+(v[6]+v[7]))
             + ((v[8]+v[9])+(v[10]+v[11])) + ((v[12]+v[13])+(v[14]+v[15]));
    float run = ts;
    #pragma unroll
    for (int o=1;o<32;o<<=1){
      float nb = __shfl_up_sync(0xffffffffu, run, o);
      if (lane>=o) run += nb;
    }
    if (lane==31) warptot[warp] = run;
    __syncthreads();
    float wb = 0.f;
    #pragma unroll
    for (int w=0;w<4;w++) if (w<warp) wb += warptot[w];
    chunkP[tid] = wb + run - ts;   // exclusive prefix: sum of s[0..base-1]
    if (tid==0){
      int a = min(min(iscr[20],iscr[21]),min(iscr[22],iscr[23]));
      int b = min(min(iscr[24],iscr[25]),min(iscr[26],iscr[27]));
      int c2= max(max(iscr[28],iscr[29]),max(iscr[30],iscr[31]));
      sh_v1=(a==0x7fffffff)?1:a;
      sh_li=(b==0x7fffffff)?v0:b;
      sh_ri=(c2<0)?p0:c2;
    }
  }
  __syncthreads();

  // ---- final: all within warp 0 (no more block barriers) ----
  if (warp==0){
    const int v1 = sh_v1;
    if (lane < 5){
      int i = v0;
      if      (lane==1) i = p0-2;
      else if (lane==2) i = p0;
      else if (lane==3) i = v1-2;
      else if (lane==4) i = vlast-2;
      if (i < 0) i = 0;
      float p = chunkP[i>>4];
      int b0 = i & ~15;
      #pragma unroll
      for (int t=0;t<16;t++){ if (b0+t<=i) p += xp[b0+t]; }
      qP[lane] = p;
    }
    __syncwarp();

    if (lane==0){
      const int li = sh_li, ri = sh_ri;
      float Pv0=qP[0], Pp2=qP[1], Pp0=qP[2], Pv12=qP[3], Pvl2=qP[4];
      float sv0 = xp[v0], sp1 = xp[p0-1], sp0v = xp[p0];
      float sv11 = xp[v1-1], svl1 = xp[vlast-1];
      float A1r = (p0-2    >= v0) ? (0.5f*(sv0 + sp1)  + (Pp2  - Pv0)) : 0.f;
      float A2r = (v1-2    >= p0) ? (0.5f*(sp0v+ sv11) + (Pv12 - Pp0)) : 0.f;
      float PAr = (vlast-2 >= v0) ? (0.5f*(sv0 + svl1) + (Pvl2 - Pv0)) : 0.f;

      const float n = 2048.f;
      float var = (sq_t - sm_t*sm_t/n) / (n - 1.f);
      var = fmaxf(var, 0.f);
      float stdv = sqrtf(var);
      float mean_amp = (2.f*mag_t) / n;
      bool gate = (np>=1) && (nv>=2);
      float PA=0.f, A2=0.f, PH=0.f, A1=0.f, PW=0.f;
      if (gate){
        PA = PAr / 30.0f;
        A2 = A2r / 30.0f;
        A1 = A1r / 30.0f;
        PH = sp0v - sv0;
        PW = (float)(ri - li) / 30.0f;
      }
      float* o = out + row*10;
      o[0]=mx_t; o[1]=mx_t-mn_t; o[2]=var; o[3]=stdv; o[4]=mean_amp;
      o[5]=PA;   o[6]=A2;        o[7]=PH;  o[8]=A1;   o[9]=PW;
    }
  }
}

extern "C" void kernel_launch(void* const* d_in, const int* in_sizes, int n_in,
                              void* d_out, int out_size) {
  const float* x = (const float*)d_in[0];
  float* out = (float*)d_out;
  (void)in_sizes; (void)n_in; (void)out_size;
  feat_kernel<<<32768, 128>>>(x, out);
}